// round 1
// baseline (speedup 1.0000x reference)
#include <cuda_runtime.h>
#include <cstdint>

#define NCN 16384
#define NPN 131072
#define ECN 131072
#define EPN 2097152
#define BGR 256
#define DIM 128

// ---------------- scratch (device globals; no allocations allowed) ----------------
__device__ float g_deg_c[2 * NCN];            // [ns(outdeg) | nd(indeg)]
__device__ float g_deg_p[2 * NPN];
__device__ float g_agg_c[(size_t)NCN * DIM];
__device__ float g_h_c[(size_t)NCN * DIM];
__device__ float g_agg_p[(size_t)NPN * DIM];
__device__ float g_h_p[(size_t)NPN * DIM];
__device__ float g_pool[BGR * 2 * DIM];       // combined [B, 256]
__device__ float g_cnt[2 * BGR];              // [cnt_c | cnt_p]

// ---------------- helpers ----------------
__device__ __forceinline__ void red_add_v4(float* p, float4 v) {
    asm volatile("red.global.add.v4.f32 [%0], {%1, %2, %3, %4};"
                 :: "l"(p), "f"(v.x), "f"(v.y), "f"(v.z), "f"(v.w) : "memory");
}

// ---------------- degree kernels ----------------
__global__ void count_deg(const int* __restrict__ src, const int* __restrict__ dst,
                          float* __restrict__ deg, int E, int N) {
    int i = blockIdx.x * blockDim.x + threadIdx.x;
    int st = gridDim.x * blockDim.x;
    for (; i < E; i += st) {
        atomicAdd(&deg[src[i]], 1.0f);
        atomicAdd(&deg[N + dst[i]], 1.0f);
    }
}

__global__ void finalize_deg(float* __restrict__ deg, int n) {
    int i = blockIdx.x * blockDim.x + threadIdx.x;
    int st = gridDim.x * blockDim.x;
    for (; i < n; i += st) deg[i] = rsqrtf(fmaxf(deg[i], 1.0f));
}

// ---------------- scatter (SpMM aggregation): agg[dst] += x[src] * ns[src] ----------------
// generic width (used for F=74), scalar atomics
__global__ void scatter_gen(const float* __restrict__ x, const float* __restrict__ ns,
                            const int* __restrict__ src, const int* __restrict__ dst,
                            float* __restrict__ agg, int E, int F) {
    int w = (blockIdx.x * blockDim.x + threadIdx.x) >> 5;
    int lane = threadIdx.x & 31;
    int nw = (gridDim.x * blockDim.x) >> 5;
    for (int e = w; e < E; e += nw) {
        int s = src[e], d = dst[e];
        float sc = ns[s];
        const float* xr = x + (size_t)s * F;
        float* ar = agg + (size_t)d * F;
        for (int k = lane; k < F; k += 32) atomicAdd(&ar[k], xr[k] * sc);
    }
}

// width 128, one warp per edge, float4 gather + vector red
__global__ void scatter128(const float* __restrict__ x, const float* __restrict__ ns,
                           const int* __restrict__ src, const int* __restrict__ dst,
                           float* __restrict__ agg, int E) {
    int w = (blockIdx.x * blockDim.x + threadIdx.x) >> 5;
    int lane = threadIdx.x & 31;
    int nw = (gridDim.x * blockDim.x) >> 5;
    for (int e = w; e < E; e += nw) {
        int s = src[e], d = dst[e];
        float sc = ns[s];
        float4 v = reinterpret_cast<const float4*>(x + (size_t)s * DIM)[lane];
        v.x *= sc; v.y *= sc; v.z *= sc; v.w *= sc;
        red_add_v4(agg + (size_t)d * DIM + lane * 4, v);
    }
}

// ---------------- GEMM with fused epilogue: out = act((A @ W) * nd[:,None] + b) ----------------
// A: [N, K] row-major, W: [K, 128], out: [N, 128]
__global__ __launch_bounds__(256) void gemm_epi(
    const float* __restrict__ A, int N, int K,
    const float* __restrict__ W, const float* __restrict__ bias,
    const float* __restrict__ nd, float* __restrict__ out, int do_relu) {
    __shared__ float As[8][64];
    __shared__ float Ws[8][128];
    int r0 = blockIdx.x * 64;
    int tid = threadIdx.x;
    int tx = tid & 31;   // col group: cols tx*4 .. tx*4+3
    int ty = tid >> 5;   // row group: rows ty*8 .. ty*8+7
    float acc[8][4];
#pragma unroll
    for (int i = 0; i < 8; i++)
#pragma unroll
        for (int j = 0; j < 4; j++) acc[i][j] = 0.0f;

    for (int kk = 0; kk < K; kk += 8) {
        // load A tile 64x8 (store transposed)
#pragma unroll
        for (int i = tid; i < 64 * 8; i += 256) {
            int r = i >> 3, c = i & 7;
            int gr = r0 + r, gc = kk + c;
            As[c][r] = (gr < N && gc < K) ? A[(size_t)gr * K + gc] : 0.0f;
        }
        // load W tile 8x128
#pragma unroll
        for (int i = tid; i < 8 * 128; i += 256) {
            int c = i >> 7, j = i & 127;
            int gc = kk + c;
            Ws[c][j] = (gc < K) ? W[(size_t)gc * 128 + j] : 0.0f;
        }
        __syncthreads();
#pragma unroll
        for (int k = 0; k < 8; k++) {
            float4 a0 = *reinterpret_cast<const float4*>(&As[k][ty * 8]);
            float4 a1 = *reinterpret_cast<const float4*>(&As[k][ty * 8 + 4]);
            float4 wv = *reinterpret_cast<const float4*>(&Ws[k][tx * 4]);
            float a[8] = {a0.x, a0.y, a0.z, a0.w, a1.x, a1.y, a1.z, a1.w};
            float wj[4] = {wv.x, wv.y, wv.z, wv.w};
#pragma unroll
            for (int i = 0; i < 8; i++)
#pragma unroll
                for (int j = 0; j < 4; j++) acc[i][j] += a[i] * wj[j];
        }
        __syncthreads();
    }
    // epilogue
#pragma unroll
    for (int i = 0; i < 8; i++) {
        int r = r0 + ty * 8 + i;
        if (r >= N) break;
        float sc = nd[r];
        float4 o;
        int c = tx * 4;
        o.x = acc[i][0] * sc + bias[c + 0];
        o.y = acc[i][1] * sc + bias[c + 1];
        o.z = acc[i][2] * sc + bias[c + 2];
        o.w = acc[i][3] * sc + bias[c + 3];
        if (do_relu) {
            o.x = fmaxf(o.x, 0.f); o.y = fmaxf(o.y, 0.f);
            o.z = fmaxf(o.z, 0.f); o.w = fmaxf(o.w, 0.f);
        }
        *reinterpret_cast<float4*>(out + (size_t)r * 128 + c) = o;
    }
}

// ---------------- pooling ----------------
__global__ void pool_sum(const float* __restrict__ h, const int* __restrict__ gid,
                         float* __restrict__ pool, float* __restrict__ cnt,
                         int N, int colOff) {
    int w = (blockIdx.x * blockDim.x + threadIdx.x) >> 5;
    int lane = threadIdx.x & 31;
    int nw = (gridDim.x * blockDim.x) >> 5;
    for (int n = w; n < N; n += nw) {
        int g = gid[n];
        float4 v = reinterpret_cast<const float4*>(h + (size_t)n * DIM)[lane];
        red_add_v4(pool + (size_t)g * 256 + colOff + lane * 4, v);
        if (lane == 0) atomicAdd(&cnt[g], 1.0f);
    }
}

__global__ void pool_div(float* __restrict__ pool, const float* __restrict__ cntc,
                         const float* __restrict__ cntp) {
    int b = blockIdx.x, t = threadIdx.x; // 256 threads
    float c = (t < 128) ? cntc[b] : cntp[b];
    pool[b * 256 + t] /= fmaxf(c, 1.0f);
}

// ---------------- predictor MLP: out[b] = relu(comb@Wf1+bf1) @ Wf2 + bf2 ----------------
__global__ void mlp_kernel(const float* __restrict__ pool, const float* __restrict__ Wf1,
                           const float* __restrict__ bf1, const float* __restrict__ Wf2,
                           const float* __restrict__ bf2, float* __restrict__ out) {
    __shared__ float comb[256];
    __shared__ float red[4];
    int b = blockIdx.x, t = threadIdx.x; // 128 threads
    comb[t] = pool[b * 256 + t];
    comb[t + 128] = pool[b * 256 + 128 + t];
    __syncthreads();
    float acc = 0.0f;
#pragma unroll 8
    for (int k = 0; k < 256; k++) acc += comb[k] * Wf1[k * 128 + t];
    float h = fmaxf(acc + bf1[t], 0.0f);
    float v = h * Wf2[t];
#pragma unroll
    for (int o = 16; o > 0; o >>= 1) v += __shfl_xor_sync(0xFFFFFFFFu, v, o);
    if ((t & 31) == 0) red[t >> 5] = v;
    __syncthreads();
    if (t == 0) out[b] = red[0] + red[1] + red[2] + red[3] + bf2[0];
}

// ---------------- launch ----------------
extern "C" void kernel_launch(void* const* d_in, const int* in_sizes, int n_in,
                              void* d_out, int out_size) {
    const float* cf  = (const float*)d_in[0];
    const float* pf  = (const float*)d_in[1];
    const int* c_src = (const int*)d_in[2];
    const int* c_dst = (const int*)d_in[3];
    const int* p_src = (const int*)d_in[4];
    const int* p_dst = (const int*)d_in[5];
    const int* c_gid = (const int*)d_in[6];
    const int* p_gid = (const int*)d_in[7];
    const float* Wc1 = (const float*)d_in[8];
    const float* bc1 = (const float*)d_in[9];
    const float* Wc2 = (const float*)d_in[10];
    const float* bc2 = (const float*)d_in[11];
    const float* Wp1 = (const float*)d_in[12];
    const float* bp1 = (const float*)d_in[13];
    const float* Wp2 = (const float*)d_in[14];
    const float* bp2 = (const float*)d_in[15];
    const float* Wf1 = (const float*)d_in[16];
    const float* bf1 = (const float*)d_in[17];
    const float* Wf2 = (const float*)d_in[18];
    const float* bf2 = (const float*)d_in[19];
    float* out = (float*)d_out;

    float *degc, *degp, *aggc, *hc, *aggp, *hp, *pool, *cnt;
    cudaGetSymbolAddress((void**)&degc, g_deg_c);
    cudaGetSymbolAddress((void**)&degp, g_deg_p);
    cudaGetSymbolAddress((void**)&aggc, g_agg_c);
    cudaGetSymbolAddress((void**)&hc,   g_h_c);
    cudaGetSymbolAddress((void**)&aggp, g_agg_p);
    cudaGetSymbolAddress((void**)&hp,   g_h_p);
    cudaGetSymbolAddress((void**)&pool, g_pool);
    cudaGetSymbolAddress((void**)&cnt,  g_cnt);

    // ---- degrees (ns = rsqrt(max(outdeg,1)), nd = rsqrt(max(indeg,1))) ----
    cudaMemsetAsync(degc, 0, sizeof(float) * 2 * NCN);
    cudaMemsetAsync(degp, 0, sizeof(float) * 2 * NPN);
    count_deg<<<512, 256>>>(c_src, c_dst, degc, ECN, NCN);
    count_deg<<<2048, 256>>>(p_src, p_dst, degp, EPN, NPN);
    finalize_deg<<<(2 * NCN + 255) / 256, 256>>>(degc, 2 * NCN);
    finalize_deg<<<(2 * NPN + 255) / 256, 256>>>(degp, 2 * NPN);

    // ---- compound layer 1 (F_in = 74) ----
    cudaMemsetAsync(aggc, 0, sizeof(float) * (size_t)NCN * 74);
    scatter_gen<<<2048, 256>>>(cf, degc, c_src, c_dst, aggc, ECN, 74);
    gemm_epi<<<NCN / 64, 256>>>(aggc, NCN, 74, Wc1, bc1, degc + NCN, hc, 1);
    // ---- compound layer 2 ----
    cudaMemsetAsync(aggc, 0, sizeof(float) * (size_t)NCN * DIM);
    scatter128<<<2048, 256>>>(hc, degc, c_src, c_dst, aggc, ECN);
    gemm_epi<<<NCN / 64, 256>>>(aggc, NCN, 128, Wc2, bc2, degc + NCN, hc, 1);

    // ---- protein layer 1 ----
    cudaMemsetAsync(aggp, 0, sizeof(float) * (size_t)NPN * DIM);
    scatter128<<<8192, 256>>>(pf, degp, p_src, p_dst, aggp, EPN);
    gemm_epi<<<NPN / 64, 256>>>(aggp, NPN, 128, Wp1, bp1, degp + NPN, hp, 1);
    // ---- protein layer 2 ----
    cudaMemsetAsync(aggp, 0, sizeof(float) * (size_t)NPN * DIM);
    scatter128<<<8192, 256>>>(hp, degp, p_src, p_dst, aggp, EPN);
    gemm_epi<<<NPN / 64, 256>>>(aggp, NPN, 128, Wp2, bp2, degp + NPN, hp, 1);

    // ---- mean pooling into combined [B, 256] ----
    cudaMemsetAsync(pool, 0, sizeof(float) * BGR * 256);
    cudaMemsetAsync(cnt, 0, sizeof(float) * 2 * BGR);
    pool_sum<<<512, 256>>>(hc, c_gid, pool, cnt, NCN, 0);
    pool_sum<<<2048, 256>>>(hp, p_gid, pool, cnt + BGR, NPN, 128);
    pool_div<<<BGR, 256>>>(pool, cnt, cnt + BGR);

    // ---- predictor MLP ----
    mlp_kernel<<<BGR, 128>>>(pool, Wf1, bf1, Wf2, bf2, out);
}

// round 5
// speedup vs baseline: 1.5131x; 1.5131x over previous
#include <cuda_runtime.h>
#include <cstdint>

#define NCN 16384
#define NPN 131072
#define ECN 131072
#define EPN 2097152
#define BGR 256
#define DIM 128

// ---------------- scratch (device globals) ----------------
__device__ int   g_dout_c[NCN], g_din_c[NCN];
__device__ int   g_dout_p[NPN], g_din_p[NPN];
__device__ float g_ns_c[NCN], g_nd_c[NCN];
__device__ float g_ns_p[NPN], g_nd_p[NPN];
__device__ int   g_start_c[NCN], g_cur_c[NCN];
__device__ int   g_start_p[NPN], g_cur_p[NPN];
__device__ int   g_bsum_c[256], g_bsum_p[256];
__device__ int   g_esrc_c[ECN];
__device__ int   g_esrc_p[EPN];
__device__ float g_agg_c[(size_t)NCN * DIM];   // tf32 bits, row-major
__device__ float g_agg_p[(size_t)NPN * DIM];   // tf32 bits, row-major
__device__ float g_h_c[(size_t)NCN * DIM];
__device__ float g_h_p[(size_t)NPN * DIM];
__device__ float g_wt[4][DIM * DIM];           // tf32 bits, [k][n] row-major, zero-padded
__device__ float g_pool[BGR * 2 * DIM];
__device__ float g_cnt[2 * BGR];

// ---------------- helpers ----------------
__device__ __forceinline__ uint32_t f2tf32(float f) {
    uint32_t r;
    asm("cvt.rna.tf32.f32 %0, %1;" : "=r"(r) : "f"(f));
    return r;
}
__device__ __forceinline__ void red_add_v4(float* p, float4 v) {
    asm volatile("red.global.add.v4.f32 [%0], {%1, %2, %3, %4};"
                 :: "l"(p), "f"(v.x), "f"(v.y), "f"(v.z), "f"(v.w) : "memory");
}
__device__ __forceinline__ void mma_tf32(float* c, const uint32_t* a, const uint32_t* b) {
    asm volatile(
        "mma.sync.aligned.m16n8k8.row.col.f32.tf32.tf32.f32 "
        "{%0, %1, %2, %3}, {%4, %5, %6, %7}, {%8, %9}, {%0, %1, %2, %3};"
        : "+f"(c[0]), "+f"(c[1]), "+f"(c[2]), "+f"(c[3])
        : "r"(a[0]), "r"(a[1]), "r"(a[2]), "r"(a[3]), "r"(b[0]), "r"(b[1]));
}

// ---------------- degree / CSR kernels ----------------
__global__ void count_deg_i(const int* __restrict__ src, const int* __restrict__ dst,
                            int* __restrict__ dout, int* __restrict__ din, int E) {
    int i = blockIdx.x * blockDim.x + threadIdx.x;
    int st = gridDim.x * blockDim.x;
    for (; i < E; i += st) {
        atomicAdd(&dout[src[i]], 1);
        atomicAdd(&din[dst[i]], 1);
    }
}

__global__ void make_rsqrt(const int* __restrict__ dout, const int* __restrict__ din,
                           float* __restrict__ ns, float* __restrict__ nd, int n) {
    int i = blockIdx.x * blockDim.x + threadIdx.x;
    if (i < n) {
        ns[i] = rsqrtf((float)max(dout[i], 1));
        nd[i] = rsqrtf((float)max(din[i], 1));
    }
}

__global__ void scan_block(const int* __restrict__ din, int* __restrict__ excl,
                           int* __restrict__ bsum, int n) {
    __shared__ int s[1024];
    int gid = blockIdx.x * 1024 + threadIdx.x;
    int v = (gid < n) ? din[gid] : 0;
    s[threadIdx.x] = v;
    __syncthreads();
#pragma unroll
    for (int o = 1; o < 1024; o <<= 1) {
        int t = (threadIdx.x >= o) ? s[threadIdx.x - o] : 0;
        __syncthreads();
        s[threadIdx.x] += t;
        __syncthreads();
    }
    if (gid < n) excl[gid] = s[threadIdx.x] - v;
    if (threadIdx.x == 1023) bsum[blockIdx.x] = s[1023];
}

__global__ void scan_sums(int* __restrict__ bsum, int nb) {
    __shared__ int s[256];
    int v = (threadIdx.x < nb) ? bsum[threadIdx.x] : 0;
    s[threadIdx.x] = v;
    __syncthreads();
#pragma unroll
    for (int o = 1; o < 256; o <<= 1) {
        int t = (threadIdx.x >= o) ? s[threadIdx.x - o] : 0;
        __syncthreads();
        s[threadIdx.x] += t;
        __syncthreads();
    }
    if (threadIdx.x < nb) bsum[threadIdx.x] = s[threadIdx.x] - v;  // exclusive
}

__global__ void scan_add(int* __restrict__ excl, const int* __restrict__ bsum, int n) {
    int gid = blockIdx.x * 1024 + threadIdx.x;
    if (gid < n) excl[gid] += bsum[blockIdx.x];
}

__global__ void csr_fill(const int* __restrict__ src, const int* __restrict__ dst,
                         const int* __restrict__ start, int* __restrict__ cur,
                         int* __restrict__ esrc, int E) {
    int i = blockIdx.x * blockDim.x + threadIdx.x;
    int st = gridDim.x * blockDim.x;
    for (; i < E; i += st) {
        int d = dst[i];
        int p = start[d] + atomicAdd(&cur[d], 1);
        esrc[p] = src[i];
    }
}

// -------- gather-aggregate (warp per node), writes row-major tf32 bits --------
__global__ void gather128(const float* __restrict__ x, const float* __restrict__ ns,
                          const int* __restrict__ start, const int* __restrict__ din,
                          const int* __restrict__ esrc, float* __restrict__ agg, int N) {
    int w = (blockIdx.x * blockDim.x + threadIdx.x) >> 5;
    int lane = threadIdx.x & 31;
    int nw = (gridDim.x * blockDim.x) >> 5;
    const float4* x4 = reinterpret_cast<const float4*>(x);
    for (int node = w; node < N; node += nw) {
        int p = start[node];
        int e1 = p + din[node];
        float4 acc = make_float4(0.f, 0.f, 0.f, 0.f);
        for (; p + 1 < e1; p += 2) {
            int sa = esrc[p], sb = esrc[p + 1];
            float fa = ns[sa], fb = ns[sb];
            float4 va = x4[(size_t)sa * 32 + lane];
            float4 vb = x4[(size_t)sb * 32 + lane];
            acc.x += va.x * fa + vb.x * fb;
            acc.y += va.y * fa + vb.y * fb;
            acc.z += va.z * fa + vb.z * fb;
            acc.w += va.w * fa + vb.w * fb;
        }
        if (p < e1) {
            int sa = esrc[p];
            float fa = ns[sa];
            float4 va = x4[(size_t)sa * 32 + lane];
            acc.x += va.x * fa; acc.y += va.y * fa;
            acc.z += va.z * fa; acc.w += va.w * fa;
        }
        uint4 t;
        t.x = f2tf32(acc.x); t.y = f2tf32(acc.y);
        t.z = f2tf32(acc.z); t.w = f2tf32(acc.w);
        reinterpret_cast<uint4*>(agg)[(size_t)node * 32 + lane] = t;
    }
}

// F=74 variant (pads K to 128 with zeros)
__global__ void gather74(const float* __restrict__ x, const float* __restrict__ ns,
                         const int* __restrict__ start, const int* __restrict__ din,
                         const int* __restrict__ esrc, float* __restrict__ agg, int N) {
    int w = (blockIdx.x * blockDim.x + threadIdx.x) >> 5;
    int lane = threadIdx.x & 31;
    int nw = (gridDim.x * blockDim.x) >> 5;
    for (int node = w; node < N; node += nw) {
        int p = start[node];
        int e1 = p + din[node];
        float a0 = 0.f, a1 = 0.f, a2 = 0.f, a3 = 0.f;
        int k0 = lane * 4;
        for (; p < e1; p++) {
            int s = esrc[p];
            float sc = ns[s];
            const float* xr = x + (size_t)s * 74;
            if (k0 + 3 < 74) {
                a0 += sc * xr[k0]; a1 += sc * xr[k0 + 1];
                a2 += sc * xr[k0 + 2]; a3 += sc * xr[k0 + 3];
            } else {
                if (k0 < 74) a0 += sc * xr[k0];
                if (k0 + 1 < 74) a1 += sc * xr[k0 + 1];
                if (k0 + 2 < 74) a2 += sc * xr[k0 + 2];
                if (k0 + 3 < 74) a3 += sc * xr[k0 + 3];
            }
        }
        uint4 t;
        t.x = f2tf32(a0); t.y = f2tf32(a1); t.z = f2tf32(a2); t.w = f2tf32(a3);
        reinterpret_cast<uint4*>(agg)[(size_t)node * 32 + lane] = t;
    }
}

// ---------------- W pre-pack: tf32 bits, [k][n] row-major, zero pad k>=Kreal ----------------
__global__ void prep_w(const float* __restrict__ W, int Kreal, float* __restrict__ out) {
    int idx = blockIdx.x * blockDim.x + threadIdx.x;  // 16384
    int k = idx >> 7, n = idx & 127;
    float v = (k < Kreal) ? W[(size_t)k * 128 + n] : 0.f;
    reinterpret_cast<uint32_t*>(out)[idx] = f2tf32(v);
}

// ---------------- mma.sync tf32 GEMM: out = relu((A @ W) * nd[:,None] + b) ----------------
// A: [N,128] tf32 bits row-major; Wt: [128][128] tf32 bits k-major; out: [N,128] fp32
// block = 256 threads = 8 warps; CTA tile 128x128; warp tile 32x64
#define AS_STRIDE 132
#define WS_STRIDE 136
#define SMEM_ELEMS (128 * AS_STRIDE + 128 * WS_STRIDE)
__global__ __launch_bounds__(256) void gemm_mma(
    const float* __restrict__ A, const float* __restrict__ Wt,
    const float* __restrict__ bias, const float* __restrict__ nd,
    float* __restrict__ out) {
    extern __shared__ uint32_t sm[];
    uint32_t* As = sm;                       // [128][AS_STRIDE]
    uint32_t* Ws = sm + 128 * AS_STRIDE;     // [128][WS_STRIDE]
    int tid = threadIdx.x;

    const uint4* Ag = reinterpret_cast<const uint4*>(A) + (size_t)blockIdx.x * 4096;
    const uint4* Wg = reinterpret_cast<const uint4*>(Wt);
#pragma unroll 4
    for (int i = tid; i < 4096; i += 256) {
        int r = i >> 5, c = i & 31;
        *reinterpret_cast<uint4*>(&As[r * AS_STRIDE + c * 4]) = Ag[i];
    }
#pragma unroll 4
    for (int i = tid; i < 4096; i += 256) {
        int r = i >> 5, c = i & 31;
        *reinterpret_cast<uint4*>(&Ws[r * WS_STRIDE + c * 4]) = Wg[i];
    }
    __syncthreads();

    int w = tid >> 5, lane = tid & 31;
    int mrow = (w >> 1) * 32;        // 4 row groups
    int ncol = (w & 1) * 64;         // 2 col groups
    int qr = lane >> 2, ql = lane & 3;

    float acc[2][8][4];
#pragma unroll
    for (int mt = 0; mt < 2; mt++)
#pragma unroll
        for (int nt = 0; nt < 8; nt++)
#pragma unroll
            for (int j = 0; j < 4; j++) acc[mt][nt][j] = 0.f;

#pragma unroll
    for (int k0 = 0; k0 < 128; k0 += 8) {
        uint32_t a[2][4], b[8][2];
#pragma unroll
        for (int mt = 0; mt < 2; mt++) {
            int r0 = mrow + mt * 16 + qr;
            a[mt][0] = As[r0 * AS_STRIDE + k0 + ql];
            a[mt][1] = As[(r0 + 8) * AS_STRIDE + k0 + ql];
            a[mt][2] = As[r0 * AS_STRIDE + k0 + ql + 4];
            a[mt][3] = As[(r0 + 8) * AS_STRIDE + k0 + ql + 4];
        }
#pragma unroll
        for (int nt = 0; nt < 8; nt++) {
            int nc = ncol + nt * 8 + qr;
            b[nt][0] = Ws[(k0 + ql) * WS_STRIDE + nc];
            b[nt][1] = Ws[(k0 + ql + 4) * WS_STRIDE + nc];
        }
#pragma unroll
        for (int mt = 0; mt < 2; mt++)
#pragma unroll
            for (int nt = 0; nt < 8; nt++)
                mma_tf32(acc[mt][nt], a[mt], b[nt]);
    }

    // epilogue: scale by nd, add bias, relu
    int rowbase = blockIdx.x * 128 + mrow;
#pragma unroll
    for (int mt = 0; mt < 2; mt++) {
        int r_lo = rowbase + mt * 16 + qr;
        int r_hi = r_lo + 8;
        float s_lo = nd[r_lo], s_hi = nd[r_hi];
        float* o_lo = out + (size_t)r_lo * 128;
        float* o_hi = out + (size_t)r_hi * 128;
#pragma unroll
        for (int nt = 0; nt < 8; nt++) {
            int c = ncol + nt * 8 + 2 * ql;
            float b0 = bias[c], b1 = bias[c + 1];
            float2 v0, v1;
            v0.x = fmaxf(acc[mt][nt][0] * s_lo + b0, 0.f);
            v0.y = fmaxf(acc[mt][nt][1] * s_lo + b1, 0.f);
            v1.x = fmaxf(acc[mt][nt][2] * s_hi + b0, 0.f);
            v1.y = fmaxf(acc[mt][nt][3] * s_hi + b1, 0.f);
            *reinterpret_cast<float2*>(o_lo + c) = v0;
            *reinterpret_cast<float2*>(o_hi + c) = v1;
        }
    }
}

// ---------------- pooling ----------------
__global__ void pool_sum(const float* __restrict__ h, const int* __restrict__ gid,
                         float* __restrict__ pool, float* __restrict__ cnt,
                         int N, int colOff) {
    int w = (blockIdx.x * blockDim.x + threadIdx.x) >> 5;
    int lane = threadIdx.x & 31;
    int nw = (gridDim.x * blockDim.x) >> 5;
    for (int n = w; n < N; n += nw) {
        int g = gid[n];
        float4 v = reinterpret_cast<const float4*>(h + (size_t)n * DIM)[lane];
        red_add_v4(pool + (size_t)g * 256 + colOff + lane * 4, v);
        if (lane == 0) atomicAdd(&cnt[g], 1.0f);
    }
}

__global__ void pool_div(float* __restrict__ pool, const float* __restrict__ cntc,
                         const float* __restrict__ cntp) {
    int b = blockIdx.x, t = threadIdx.x;
    float c = (t < 128) ? cntc[b] : cntp[b];
    pool[b * 256 + t] /= fmaxf(c, 1.0f);
}

// ---------------- predictor MLP ----------------
__global__ void mlp_kernel(const float* __restrict__ pool, const float* __restrict__ Wf1,
                           const float* __restrict__ bf1, const float* __restrict__ Wf2,
                           const float* __restrict__ bf2, float* __restrict__ out) {
    __shared__ float comb[256];
    __shared__ float red[4];
    int b = blockIdx.x, t = threadIdx.x;  // 128 threads
    comb[t] = pool[b * 256 + t];
    comb[t + 128] = pool[b * 256 + 128 + t];
    __syncthreads();
    float acc = 0.0f;
#pragma unroll 8
    for (int k = 0; k < 256; k++) acc += comb[k] * Wf1[k * 128 + t];
    float h = fmaxf(acc + bf1[t], 0.0f);
    float v = h * Wf2[t];
#pragma unroll
    for (int o = 16; o > 0; o >>= 1) v += __shfl_xor_sync(0xFFFFFFFFu, v, o);
    if ((t & 31) == 0) red[t >> 5] = v;
    __syncthreads();
    if (t == 0) out[b] = red[0] + red[1] + red[2] + red[3] + bf2[0];
}

// ---------------- launch ----------------
extern "C" void kernel_launch(void* const* d_in, const int* in_sizes, int n_in,
                              void* d_out, int out_size) {
    const float* cf  = (const float*)d_in[0];
    const float* pf  = (const float*)d_in[1];
    const int* c_src = (const int*)d_in[2];
    const int* c_dst = (const int*)d_in[3];
    const int* p_src = (const int*)d_in[4];
    const int* p_dst = (const int*)d_in[5];
    const int* c_gid = (const int*)d_in[6];
    const int* p_gid = (const int*)d_in[7];
    const float* Wc1 = (const float*)d_in[8];
    const float* bc1 = (const float*)d_in[9];
    const float* Wc2 = (const float*)d_in[10];
    const float* bc2 = (const float*)d_in[11];
    const float* Wp1 = (const float*)d_in[12];
    const float* bp1 = (const float*)d_in[13];
    const float* Wp2 = (const float*)d_in[14];
    const float* bp2 = (const float*)d_in[15];
    const float* Wf1 = (const float*)d_in[16];
    const float* bf1 = (const float*)d_in[17];
    const float* Wf2 = (const float*)d_in[18];
    const float* bf2 = (const float*)d_in[19];
    float* out = (float*)d_out;

    int *doutc, *dinc, *doutp, *dinp, *startc, *curc, *startp, *curp;
    int *bsumc, *bsump, *esrcc, *esrcp;
    float *nsc, *ndc, *nsp, *ndp, *aggc, *aggp, *hc, *hp, *wt, *pool, *cnt;
    cudaGetSymbolAddress((void**)&doutc, g_dout_c);
    cudaGetSymbolAddress((void**)&dinc,  g_din_c);
    cudaGetSymbolAddress((void**)&doutp, g_dout_p);
    cudaGetSymbolAddress((void**)&dinp,  g_din_p);
    cudaGetSymbolAddress((void**)&nsc,   g_ns_c);
    cudaGetSymbolAddress((void**)&ndc,   g_nd_c);
    cudaGetSymbolAddress((void**)&nsp,   g_ns_p);
    cudaGetSymbolAddress((void**)&ndp,   g_nd_p);
    cudaGetSymbolAddress((void**)&startc, g_start_c);
    cudaGetSymbolAddress((void**)&curc,  g_cur_c);
    cudaGetSymbolAddress((void**)&startp, g_start_p);
    cudaGetSymbolAddress((void**)&curp,  g_cur_p);
    cudaGetSymbolAddress((void**)&bsumc, g_bsum_c);
    cudaGetSymbolAddress((void**)&bsump, g_bsum_p);
    cudaGetSymbolAddress((void**)&esrcc, g_esrc_c);
    cudaGetSymbolAddress((void**)&esrcp, g_esrc_p);
    cudaGetSymbolAddress((void**)&aggc,  g_agg_c);
    cudaGetSymbolAddress((void**)&aggp,  g_agg_p);
    cudaGetSymbolAddress((void**)&hc,    g_h_c);
    cudaGetSymbolAddress((void**)&hp,    g_h_p);
    cudaGetSymbolAddress((void**)&wt,    g_wt);
    cudaGetSymbolAddress((void**)&pool,  g_pool);
    cudaGetSymbolAddress((void**)&cnt,   g_cnt);

    const int GEMM_SMEM = SMEM_ELEMS * 4;  // ~137 KB
    cudaFuncSetAttribute(gemm_mma, cudaFuncAttributeMaxDynamicSharedMemorySize, GEMM_SMEM);

    // ---- degrees + CSR ----
    cudaMemsetAsync(doutc, 0, sizeof(int) * NCN);
    cudaMemsetAsync(dinc,  0, sizeof(int) * NCN);
    cudaMemsetAsync(doutp, 0, sizeof(int) * NPN);
    cudaMemsetAsync(dinp,  0, sizeof(int) * NPN);
    cudaMemsetAsync(curc,  0, sizeof(int) * NCN);
    cudaMemsetAsync(curp,  0, sizeof(int) * NPN);
    count_deg_i<<<512, 256>>>(c_src, c_dst, doutc, dinc, ECN);
    count_deg_i<<<2048, 256>>>(p_src, p_dst, doutp, dinp, EPN);
    make_rsqrt<<<NCN / 256, 256>>>(doutc, dinc, nsc, ndc, NCN);
    make_rsqrt<<<NPN / 256, 256>>>(doutp, dinp, nsp, ndp, NPN);
    scan_block<<<NCN / 1024, 1024>>>(dinc, startc, bsumc, NCN);
    scan_block<<<NPN / 1024, 1024>>>(dinp, startp, bsump, NPN);
    scan_sums<<<1, 256>>>(bsumc, NCN / 1024);
    scan_sums<<<1, 256>>>(bsump, NPN / 1024);
    scan_add<<<NCN / 1024, 1024>>>(startc, bsumc, NCN);
    scan_add<<<NPN / 1024, 1024>>>(startp, bsump, NPN);
    csr_fill<<<512, 256>>>(c_src, c_dst, startc, curc, esrcc, ECN);
    csr_fill<<<2048, 256>>>(p_src, p_dst, startp, curp, esrcp, EPN);

    // ---- prepack weights (tf32 bits, k-major, zero-padded) ----
    prep_w<<<64, 256>>>(Wc1, 74,  wt + 0 * 16384);
    prep_w<<<64, 256>>>(Wc2, 128, wt + 1 * 16384);
    prep_w<<<64, 256>>>(Wp1, 128, wt + 2 * 16384);
    prep_w<<<64, 256>>>(Wp2, 128, wt + 3 * 16384);

    // ---- compound layer 1 (F=74 padded to 128) ----
    gather74<<<2048, 256>>>(cf, nsc, startc, dinc, esrcc, aggc, NCN);
    gemm_mma<<<NCN / 128, 256, GEMM_SMEM>>>(aggc, wt + 0 * 16384, bc1, ndc, hc);
    // ---- compound layer 2 ----
    gather128<<<2048, 256>>>(hc, nsc, startc, dinc, esrcc, aggc, NCN);
    gemm_mma<<<NCN / 128, 256, GEMM_SMEM>>>(aggc, wt + 1 * 16384, bc2, ndc, hc);
    // ---- protein layer 1 ----
    gather128<<<16384, 256>>>(pf, nsp, startp, dinp, esrcp, aggp, NPN);
    gemm_mma<<<NPN / 128, 256, GEMM_SMEM>>>(aggp, wt + 2 * 16384, bp1, ndp, hp);
    // ---- protein layer 2 ----
    gather128<<<16384, 256>>>(hp, nsp, startp, dinp, esrcp, aggp, NPN);
    gemm_mma<<<NPN / 128, 256, GEMM_SMEM>>>(aggp, wt + 3 * 16384, bp2, ndp, hp);

    // ---- mean pooling ----
    cudaMemsetAsync(pool, 0, sizeof(float) * BGR * 256);
    cudaMemsetAsync(cnt, 0, sizeof(float) * 2 * BGR);
    pool_sum<<<512, 256>>>(hc, c_gid, pool, cnt, NCN, 0);
    pool_sum<<<2048, 256>>>(hp, p_gid, pool, cnt + BGR, NPN, 128);
    pool_div<<<BGR, 256>>>(pool, cnt, cnt + BGR);

    // ---- predictor MLP ----
    mlp_kernel<<<BGR, 128>>>(pool, Wf1, bf1, Wf2, bf2, out);
}